// round 14
// baseline (speedup 1.0000x reference)
#include <cuda_runtime.h>
#include <cuda_fp16.h>
#include <cstdint>
#include <math.h>

// ---------------- problem constants ----------------
#define BATCH  4096
#define NPED   64
#define HD     64
#define G2     64
#define KDIM   4096
#define NB     1024
#define BN_EPS 1e-5f

// ---------------- GEMM tiling ----------------
#define BM 128
#define BNv 128
#define BK 32
#define NK (KDIM / BK)          // 128
#define STAGES 4
#define ROWB 80                 // padded row bytes (32 halves + 8 pad)
#define STAGE_BYTES (2 * 128 * ROWB)     // 20480
#define GEMM_SMEM (STAGES * STAGE_BYTES) // 81920 -> 2 CTAs/SM

// ---------------- device scratch ----------------
__device__ __half g_A [(size_t)BATCH * KDIM];   // pooled features, fp16
__device__ __half g_Bt[(size_t)NB * KDIM];      // W^T (K-major), fp16
__device__ float  g_sum[NB];
__device__ float  g_sumsq[NB];

// ---------------- helpers ----------------
__device__ __forceinline__ uint32_t h2u(__half2 h) {
    return *reinterpret_cast<uint32_t*>(&h);
}

__device__ __forceinline__ uint32_t smem_u32(const void* p) {
    uint32_t a;
    asm("{ .reg .u64 t; cvta.to.shared.u64 t, %1; cvt.u32.u64 %0, t; }"
        : "=r"(a) : "l"(p));
    return a;
}

__device__ __forceinline__ void cp16(uint32_t dst, const void* src) {
    asm volatile("cp.async.cg.shared.global [%0], [%1], 16;"
                 :: "r"(dst), "l"(src) : "memory");
}

#define CP_COMMIT() asm volatile("cp.async.commit_group;" ::: "memory")
#define CP_WAIT(n)  asm volatile("cp.async.wait_group %0;" :: "n"(n) : "memory")

#define LDM4(r0, r1, r2, r3, a)                                         \
    asm volatile("ldmatrix.sync.aligned.m8n8.x4.shared.b16 "            \
                 "{%0,%1,%2,%3}, [%4];"                                 \
                 : "=r"(r0), "=r"(r1), "=r"(r2), "=r"(r3) : "r"(a))

#define MMA16816(c, a, b)                                               \
    asm volatile("mma.sync.aligned.m16n8k16.row.col.f32.f16.f16.f32 "   \
                 "{%0,%1,%2,%3}, {%4,%5,%6,%7}, {%8,%9}, {%0,%1,%2,%3};"\
                 : "+f"((c)[0]), "+f"((c)[1]), "+f"((c)[2]), "+f"((c)[3])\
                 : "r"((a)[0]), "r"((a)[1]), "r"((a)[2]), "r"((a)[3]),  \
                   "r"((b)[0]), "r"((b)[1]))

// ---------------------------------------------------------------------------
// Kernel 1 (merged, 256 threads): blocks [0,4096) social pooling -> fp16 A
// rows; j-loop split over 4 thread groups with SMEM atomicAdd. Blocks
// [4096,5120) transpose W -> fp16 Bt. Blocks 0..3 also zero BN stats.
// ---------------------------------------------------------------------------
__global__ __launch_bounds__(256) void prep_kernel(
    const float* __restrict__ h,
    const float* __restrict__ pos,
    const float* __restrict__ W)
{
    __shared__ float buf[4224];          // pool: sp[4096]+spos[128f]; transp: 64x65=4160
    const int blk = blockIdx.x;
    const int t   = threadIdx.x;

    if (blk < BATCH) {
        // ---------------- pooling path ----------------
        float* sp = buf;
        float2* spos = reinterpret_cast<float2*>(buf + 4096);
        const int base = (blk >> 6) << 6;

        if (blk < 4) {                   // zero BN accumulators (1024 = 4 x 256)
            g_sum  [blk * 256 + t] = 0.0f;
            g_sumsq[blk * 256 + t] = 0.0f;
        }

        for (int k = t; k < 4096; k += 256) sp[k] = 0.0f;
        if (t < 64) spos[t] = reinterpret_cast<const float2*>(pos)[base + t];
        __syncthreads();

        const int local_i = blk - base;
        const float2 pi = spos[local_i];
        const float tlx = pi.x - 1.0f, tly = pi.y + 1.0f;
        const float brx = pi.x + 1.0f, bry = pi.y - 1.0f;

        const int d  = t & 63;           // hidden dim
        const int qj = t >> 6;           // j-group 0..3
        for (int j = qj; j < NPED; j += 4) {
            if (j == local_i) continue;
            const float2 pj = spos[j];
            if (pj.x >= brx || pj.x <= tlx || pj.y >= tly || pj.y <= bry) continue;
            int cx = (int)floorf((pj.x - tlx) / 2.0f * 8.0f);
            int cy = (int)floorf((tly - pj.y) / 2.0f * 8.0f);
            int cell = min(max(cx + cy * 8, 0), G2 - 1);
            atomicAdd(&sp[cell * HD + d], h[(size_t)(base + j) * HD + d]);
        }
        __syncthreads();

        // vectorized fp16 output: 512 uint4 per row, 2 per thread
        uint4* dst = reinterpret_cast<uint4*>(g_A + (size_t)blk * KDIM);
#pragma unroll
        for (int i = 0; i < 2; ++i) {
            const int c = t + i * 256;               // uint4 index
            const float4 a = *reinterpret_cast<const float4*>(&sp[c * 8]);
            const float4 b = *reinterpret_cast<const float4*>(&sp[c * 8 + 4]);
            uint4 o;
            o.x = h2u(__floats2half2_rn(a.x, a.y));
            o.y = h2u(__floats2half2_rn(a.z, a.w));
            o.z = h2u(__floats2half2_rn(b.x, b.y));
            o.w = h2u(__floats2half2_rn(b.z, b.w));
            dst[c] = o;
        }
    } else {
        // ---------------- W transpose path ----------------
        const int idx = blk - BATCH;                 // 0..1023
        const int k0  = (idx >> 4) * 64;             // 64 k-tiles
        const int n0  = (idx & 15) * 64;             // 16 n-tiles

        for (int e = t; e < 4096; e += 256) {        // 64x64 tile, pitch 65
            const int kk = e >> 6, nn = e & 63;
            buf[kk * 65 + nn] = W[(size_t)(k0 + kk) * NB + n0 + nn];
        }
        __syncthreads();

        // 512 uint4 outputs (64 rows x 8 chunks), 2 per thread
#pragma unroll
        for (int i = 0; i < 2; ++i) {
            const int e  = t + i * 256;
            const int n  = e >> 3, c8 = e & 7;
            const float* col = &buf[(c8 * 8) * 65 + n];
            uint4 o;
            o.x = h2u(__floats2half2_rn(col[0],       col[65]));
            o.y = h2u(__floats2half2_rn(col[2 * 65],  col[3 * 65]));
            o.z = h2u(__floats2half2_rn(col[4 * 65],  col[5 * 65]));
            o.w = h2u(__floats2half2_rn(col[6 * 65],  col[7 * 65]));
            reinterpret_cast<uint4*>(g_Bt + (size_t)(n0 + n) * KDIM + k0)[c8] = o;
        }
    }
}

// ---------------------------------------------------------------------------
// Kernel 2: fp16 mma.sync GEMM  X = A * W + b, fused BN column stats
// CTA 128x128, BK=32, 4-stage cp.async, 2 CTAs/SM (256 CTAs in one wave).
// Warps 2(M) x 4(N); warp tile 64x32. One __syncthreads per K-iteration.
// ---------------------------------------------------------------------------
__global__ __launch_bounds__(256, 2) void gemm_kernel(
    const __half* __restrict__ A,   // [BATCH, KDIM]
    const __half* __restrict__ Bt,  // [NB, KDIM]
    const float* __restrict__ bias,
    float* __restrict__ X)          // [BATCH, NB]
{
    extern __shared__ __align__(16) char dsm[];
    const uint32_t sbase = smem_u32(dsm);
    const int t    = threadIdx.x;
    const int warp = t >> 5, lane = t & 31;
    const int m0 = blockIdx.y * BM;
    const int n0 = blockIdx.x * BNv;
    const int warp_m = warp & 1;     // 64-row slab
    const int warp_n = warp >> 1;    // 32-col slab

    float acc[4][4][4];
#pragma unroll
    for (int i = 0; i < 4; ++i)
#pragma unroll
        for (int j = 0; j < 4; ++j)
#pragma unroll
            for (int e = 0; e < 4; ++e) acc[i][j][e] = 0.0f;

    auto load_stage = [&](int s, int kt) {
        const int kk = kt * BK;
        const uint32_t sA = sbase + (uint32_t)s * STAGE_BYTES;
        const uint32_t sB = sA + 128 * ROWB;
#pragma unroll
        for (int i = 0; i < 2; ++i) {
            const int id = t + i * 256;
            const int r = id >> 2, c = (id & 3) * 8;
            cp16(sA + r * ROWB + c * 2, A  + (size_t)(m0 + r) * KDIM + kk + c);
            cp16(sB + r * ROWB + c * 2, Bt + (size_t)(n0 + r) * KDIM + kk + c);
        }
    };

#pragma unroll
    for (int s = 0; s < STAGES - 1; ++s) {
        load_stage(s, s);
        CP_COMMIT();
    }

    const int q  = lane >> 3;   // 0..3
    const int lr = lane & 7;

    for (int kt = 0; kt < NK; ++kt) {
        CP_WAIT(2);             // stage kt resident
        __syncthreads();        // everyone done with stage kt-1 (to be overwritten)

        if (kt + STAGES - 1 < NK)
            load_stage((kt + STAGES - 1) % STAGES, kt + STAGES - 1);
        CP_COMMIT();

        const uint32_t sA = sbase + (uint32_t)(kt % STAGES) * STAGE_BYTES;
        const uint32_t sB = sA + 128 * ROWB;

#pragma unroll
        for (int ks = 0; ks < 2; ++ks) {
            uint32_t aF[4][4];
            uint32_t bF[4][2];
#pragma unroll
            for (int mi = 0; mi < 4; ++mi) {
                const int row  = warp_m * 64 + mi * 16 + (q & 1) * 8 + lr;
                const int colh = ks * 16 + (q >> 1) * 8;
                LDM4(aF[mi][0], aF[mi][1], aF[mi][2], aF[mi][3],
                     sA + row * ROWB + colh * 2);
            }
#pragma unroll
            for (int pi = 0; pi < 2; ++pi) {
                const int row  = warp_n * 32 + pi * 16 + (q >> 1) * 8 + lr;
                const int colh = ks * 16 + (q & 1) * 8;
                uint32_t r0, r1, r2, r3;
                LDM4(r0, r1, r2, r3, sB + row * ROWB + colh * 2);
                bF[pi * 2 + 0][0] = r0;  bF[pi * 2 + 0][1] = r1;
                bF[pi * 2 + 1][0] = r2;  bF[pi * 2 + 1][1] = r3;
            }
#pragma unroll
            for (int mi = 0; mi < 4; ++mi)
#pragma unroll
                for (int ni = 0; ni < 4; ++ni)
                    MMA16816(acc[mi][ni], aF[mi], bF[ni]);
        }
    }

    // epilogue: bias add, store, fused column sum/sumsq (64 rows per warp)
    const int er = lane >> 2;         // 0..7
    const int ec = (lane & 3) * 2;
#pragma unroll
    for (int ni = 0; ni < 4; ++ni) {
        const int n  = n0 + warp_n * 32 + ni * 8 + ec;
        const float b0 = bias[n], b1 = bias[n + 1];
        float s0 = 0.f, s1 = 0.f, q0 = 0.f, q1 = 0.f;
#pragma unroll
        for (int mi = 0; mi < 4; ++mi) {
            const int mrow = m0 + warp_m * 64 + mi * 16 + er;
            float v0 = acc[mi][ni][0] + b0;
            float v1 = acc[mi][ni][1] + b1;
            float v2 = acc[mi][ni][2] + b0;
            float v3 = acc[mi][ni][3] + b1;
            *reinterpret_cast<float2*>(&X[(size_t)mrow * NB + n]) =
                make_float2(v0, v1);
            *reinterpret_cast<float2*>(&X[(size_t)(mrow + 8) * NB + n]) =
                make_float2(v2, v3);
            s0 += v0 + v2;           s1 += v1 + v3;
            q0 += v0 * v0 + v2 * v2; q1 += v1 * v1 + v3 * v3;
        }
#pragma unroll
        for (int off = 4; off < 32; off <<= 1) {
            s0 += __shfl_xor_sync(0xFFFFFFFFu, s0, off);
            s1 += __shfl_xor_sync(0xFFFFFFFFu, s1, off);
            q0 += __shfl_xor_sync(0xFFFFFFFFu, q0, off);
            q1 += __shfl_xor_sync(0xFFFFFFFFu, q1, off);
        }
        if (er == 0) {
            atomicAdd(&g_sum[n],       s0);
            atomicAdd(&g_sum[n + 1],   s1);
            atomicAdd(&g_sumsq[n],     q0);
            atomicAdd(&g_sumsq[n + 1], q1);
        }
    }
}

// ---------------------------------------------------------------------------
// Kernel 3: batchnorm + ReLU, float4-vectorized, in place
// ---------------------------------------------------------------------------
__global__ __launch_bounds__(256) void apply_kernel(
    float* __restrict__ X,
    const float* __restrict__ gamma,
    const float* __restrict__ beta)
{
    const int i4 = blockIdx.x * 256 + threadIdx.x;   // float4 index
    const int c4 = i4 & (NB / 4 - 1);                // column group
    const float inv_n = 1.0f / (float)BATCH;

    float4 s  = reinterpret_cast<const float4*>(g_sum)[c4];
    float4 ss = reinterpret_cast<const float4*>(g_sumsq)[c4];
    float4 g  = reinterpret_cast<const float4*>(gamma)[c4];
    float4 be = reinterpret_cast<const float4*>(beta)[c4];
    float4 v  = reinterpret_cast<float4*>(X)[i4];

    float m, is;
    m = s.x * inv_n; is = rsqrtf(ss.x * inv_n - m * m + BN_EPS);
    v.x = fmaxf((v.x - m) * is * g.x + be.x, 0.0f);
    m = s.y * inv_n; is = rsqrtf(ss.y * inv_n - m * m + BN_EPS);
    v.y = fmaxf((v.y - m) * is * g.y + be.y, 0.0f);
    m = s.z * inv_n; is = rsqrtf(ss.z * inv_n - m * m + BN_EPS);
    v.z = fmaxf((v.z - m) * is * g.z + be.z, 0.0f);
    m = s.w * inv_n; is = rsqrtf(ss.w * inv_n - m * m + BN_EPS);
    v.w = fmaxf((v.w - m) * is * g.w + be.w, 0.0f);

    reinterpret_cast<float4*>(X)[i4] = v;
}

// ---------------------------------------------------------------------------
// launch
// ---------------------------------------------------------------------------
extern "C" void kernel_launch(void* const* d_in, const int* in_sizes, int n_in,
                              void* d_out, int out_size)
{
    const float* h_states = (const float*)d_in[0];
    const float* end_pos  = (const float*)d_in[2];
    const float* W        = (const float*)d_in[4];
    const float* b        = (const float*)d_in[5];
    const float* gamma    = (const float*)d_in[6];
    const float* beta     = (const float*)d_in[7];
    float* X = (float*)d_out;

    __half *Ap, *Btp;
    cudaGetSymbolAddress((void**)&Ap,  g_A);
    cudaGetSymbolAddress((void**)&Btp, g_Bt);

    cudaFuncSetAttribute(gemm_kernel,
                         cudaFuncAttributeMaxDynamicSharedMemorySize, GEMM_SMEM);

    prep_kernel<<<BATCH + 1024, 256>>>(h_states, end_pos, W);

    gemm_kernel<<<dim3(NB / BNv, BATCH / BM), 256, GEMM_SMEM>>>(Ap, Btp, b, X);

    apply_kernel<<<(BATCH * NB / 4) / 256, 256>>>(X, gamma, beta);
}